// round 5
// baseline (speedup 1.0000x reference)
#include <cuda_runtime.h>
#include <cstdint>

#define NUM_NODES 50000
#define INPUT_SIZE 128
#define NUM_REL 16
#define NUM_EDGES 1600000
#define CLAMP_MIN 1e-5f
#define CLAMP_MAX 0.99999f

// Node logit table: T[n][0:16] = x[n].W_src, T[n][16:32] = x[n].W_dst
__device__ float g_table[NUM_NODES * 32];

// Packed f32x2 helpers (Blackwell FFMA2 — PTX-only, ptxas won't auto-fuse).
__device__ __forceinline__ uint64_t pack2(float lo, float hi) {
    uint64_t r;
    asm("mov.b64 %0, {%1, %2};" : "=l"(r) : "f"(lo), "f"(hi));
    return r;
}
__device__ __forceinline__ void fma2(uint64_t& acc, uint64_t a, uint64_t b) {
    asm("fma.rn.f32x2 %0, %1, %2, %0;" : "+l"(acc) : "l"(a), "l"(b));
}
__device__ __forceinline__ float2 unpack2(uint64_t v) {
    float lo, hi;
    asm("mov.b64 {%0, %1}, %2;" : "=f"(lo), "=f"(hi) : "l"(v));
    return make_float2(lo, hi);
}

// ---------------------------------------------------------------------------
// Kernel A: 50000x128 @ 128x32 GEMM into g_table.
// 128 threads/block, tile 128 nodes x 32 cols. Per thread: 8 nodes x 4 cols
// as 4 node-pairs x 4 cols in FFMA2. W staged in smem (16B LDS.128 per kk),
// X pairs free from the [k][node] smem layout.
// ---------------------------------------------------------------------------
#define XPAD 132

__global__ void __launch_bounds__(128) node_logits_kernel(
    const float* __restrict__ x, const float* __restrict__ W)
{
    __shared__ float Ws[INPUT_SIZE][32];   // 16 KB [k][r]
    __shared__ float Xs[32][XPAD];         // 16.9 KB [k][node]

    const int tid = threadIdx.x;

    for (int idx = tid; idx < INPUT_SIZE * 32; idx += 128) {
        int k = idx >> 5;
        int r = idx & 31;
        Ws[k][r] = (r < NUM_REL) ? W[k * NUM_REL + r]
                                 : W[(k + INPUT_SIZE) * NUM_REL + (r - NUM_REL)];
    }

    const int node0 = blockIdx.x * 128;
    const int rg = tid & 7;    // 8 groups of 4 rel-cols
    const int ng = tid >> 3;   // 16 groups of 8 nodes

    uint64_t acc2[4][4];       // [node-pair][col]
#pragma unroll
    for (int i = 0; i < 4; ++i)
#pragma unroll
        for (int j = 0; j < 4; ++j) acc2[i][j] = 0ull;

    for (int kc = 0; kc < 4; ++kc) {
        __syncthreads();
#pragma unroll
        for (int it = 0; it < 8; ++it) {
            int s = tid + it * 128;     // 0..1023
            int row = s >> 3;           // node within tile 0..127
            int c4  = s & 7;            // float4 within 32-float k-chunk
            int gr = node0 + row;
            if (gr >= NUM_NODES) gr = NUM_NODES - 1;
            float4 v = *reinterpret_cast<const float4*>(
                &x[(size_t)gr * INPUT_SIZE + kc * 32 + c4 * 4]);
            Xs[c4 * 4 + 0][row] = v.x;
            Xs[c4 * 4 + 1][row] = v.y;
            Xs[c4 * 4 + 2][row] = v.z;
            Xs[c4 * 4 + 3][row] = v.w;
        }
        __syncthreads();

#pragma unroll
        for (int kk = 0; kk < 32; ++kk) {
            int k = kc * 32 + kk;
            float4 wv = *reinterpret_cast<const float4*>(&Ws[k][rg * 4]);
            uint64_t wd[4] = { pack2(wv.x, wv.x), pack2(wv.y, wv.y),
                               pack2(wv.z, wv.z), pack2(wv.w, wv.w) };
            float4 xa = *reinterpret_cast<const float4*>(&Xs[kk][ng * 8]);
            float4 xb = *reinterpret_cast<const float4*>(&Xs[kk][ng * 8 + 4]);
            uint64_t xp[4] = { pack2(xa.x, xa.y), pack2(xa.z, xa.w),
                               pack2(xb.x, xb.y), pack2(xb.z, xb.w) };
#pragma unroll
            for (int i = 0; i < 4; ++i)
#pragma unroll
                for (int j = 0; j < 4; ++j)
                    fma2(acc2[i][j], xp[i], wd[j]);
        }
    }

#pragma unroll
    for (int i = 0; i < 4; ++i) {
        float2 c0 = unpack2(acc2[i][0]);
        float2 c1 = unpack2(acc2[i][1]);
        float2 c2 = unpack2(acc2[i][2]);
        float2 c3 = unpack2(acc2[i][3]);
        int n0 = node0 + ng * 8 + 2 * i;
        if (n0 < NUM_NODES)
            *reinterpret_cast<float4*>(&g_table[(size_t)n0 * 32 + rg * 4]) =
                make_float4(c0.x, c1.x, c2.x, c3.x);
        if (n0 + 1 < NUM_NODES)
            *reinterpret_cast<float4*>(&g_table[(size_t)(n0 + 1) * 32 + rg * 4]) =
                make_float4(c0.y, c1.y, c2.y, c3.y);
    }
}

// ---------------------------------------------------------------------------
// Kernel B: per-edge gather + sigmoid + clamp.
// 128-thread blocks, 8 edges/thread: 16 independent gathers in flight per
// thread, 1563-block grid for SM balance (fixes R3's grid-granularity occ cap).
// ---------------------------------------------------------------------------
__global__ void __launch_bounds__(128) edge_kernel(
    const int* __restrict__ ei,
    const int* __restrict__ et,
    float* __restrict__ out)
{
    const int e0 = (blockIdx.x * 128 + threadIdx.x) * 8;
    if (e0 + 7 < NUM_EDGES) {
        int4 s4a = *reinterpret_cast<const int4*>(ei + e0);
        int4 s4b = *reinterpret_cast<const int4*>(ei + e0 + 4);
        int4 d4a = *reinterpret_cast<const int4*>(ei + NUM_EDGES + e0);
        int4 d4b = *reinterpret_cast<const int4*>(ei + NUM_EDGES + e0 + 4);
        int4 t4a = *reinterpret_cast<const int4*>(et + e0);
        int4 t4b = *reinterpret_cast<const int4*>(et + e0 + 4);

        int s[8] = {s4a.x, s4a.y, s4a.z, s4a.w, s4b.x, s4b.y, s4b.z, s4b.w};
        int d[8] = {d4a.x, d4a.y, d4a.z, d4a.w, d4b.x, d4b.y, d4b.z, d4b.w};
        int t[8] = {t4a.x, t4a.y, t4a.z, t4a.w, t4b.x, t4b.y, t4b.z, t4b.w};

        float a[8], b[8];
#pragma unroll
        for (int i = 0; i < 8; ++i) a[i] = __ldg(&g_table[s[i] * 32 + t[i]]);
#pragma unroll
        for (int i = 0; i < 8; ++i) b[i] = __ldg(&g_table[d[i] * 32 + 16 + t[i]]);

        float o[8];
#pragma unroll
        for (int i = 0; i < 8; ++i) {
            float p = 1.0f / (1.0f + __expf(-(a[i] + b[i])));
            o[i] = fminf(fmaxf(p, CLAMP_MIN), CLAMP_MAX);
        }
        *reinterpret_cast<float4*>(out + e0)     = make_float4(o[0], o[1], o[2], o[3]);
        *reinterpret_cast<float4*>(out + e0 + 4) = make_float4(o[4], o[5], o[6], o[7]);
    } else {
        for (int e = e0; e < NUM_EDGES; ++e) {
            int s = ei[e], d = ei[NUM_EDGES + e], t = et[e];
            float p = 1.0f / (1.0f + __expf(-(g_table[s * 32 + t] + g_table[d * 32 + 16 + t])));
            out[e] = fminf(fmaxf(p, CLAMP_MIN), CLAMP_MAX);
        }
    }
}

extern "C" void kernel_launch(void* const* d_in, const int* in_sizes, int n_in,
                              void* d_out, int out_size)
{
    const float* x  = (const float*)d_in[0];
    const float* W  = (const float*)d_in[1];
    const int*   ei = (const int*)d_in[2];
    const int*   et = (const int*)d_in[3];
    float* out = (float*)d_out;

    const int node_blocks = (NUM_NODES + 127) / 128;           // 391
    node_logits_kernel<<<node_blocks, 128>>>(x, W);

    const int groups = (NUM_EDGES + 7) / 8;                    // 200000
    const int edge_blocks = (groups + 127) / 128;              // 1563
    edge_kernel<<<edge_blocks, 128>>>(ei, et, out);
}